// round 1
// baseline (speedup 1.0000x reference)
#include <cuda_runtime.h>
#include <cuda_bf16.h>

// BiATT algebraic collapse:
//   softmax over axis=1 of an [N,1] tensor is identically 1.0, so
//   cfs[i] == atoms_vector and pfs[i] == amino_vector for all 4 branches.
//   cf_final = atoms @ (sum of 4 DxD blocks of Wcc) + bcc
//   pf_final = amino @ (sum of 4 DxD blocks of Wcp) + bcp
// => fold weights, then two [6144x512]@[512x512] fp32 GEMMs with bias.

#define DIM     512
#define M_ROWS  6144
#define BM      128
#define BN      128
#define BK      16
#define TM      8
#define TN      8

// scratch for folded weights (allocation-free rule: __device__ global)
__device__ float g_Wsum[2][DIM * DIM];

// ---------------------------------------------------------------- helpers
__device__ __forceinline__ unsigned long long pack2(float lo, float hi) {
    unsigned long long r;
    asm("mov.b64 %0, {%1, %2};" : "=l"(r) : "f"(lo), "f"(hi));
    return r;
}
__device__ __forceinline__ void ffma2(unsigned long long& c,
                                      unsigned long long a,
                                      unsigned long long b) {
    asm("fma.rn.f32x2 %0, %1, %2, %0;" : "+l"(c) : "l"(a), "l"(b));
}
__device__ __forceinline__ unsigned long long add2(unsigned long long a,
                                                   unsigned long long b) {
    unsigned long long r;
    asm("add.rn.f32x2 %0, %1, %2;" : "=l"(r) : "l"(a), "l"(b));
    return r;
}

// ---------------------------------------------------- weight fold kernel
__global__ void fold_weights_kernel(const float* __restrict__ Wcc,
                                    const float* __restrict__ Wcp) {
    int idx = blockIdx.x * blockDim.x + threadIdx.x;   // 0 .. 512*512-1
    if (idx >= DIM * DIM) return;
    int k = idx / DIM;
    int j = idx - k * DIM;
    float s0 = 0.f, s1 = 0.f;
#pragma unroll
    for (int b = 0; b < 4; b++) {
        s0 += Wcc[(size_t)(b * DIM + k) * DIM + j];
        s1 += Wcp[(size_t)(b * DIM + k) * DIM + j];
    }
    g_Wsum[0][idx] = s0;
    g_Wsum[1][idx] = s1;
}

// ------------------------------------------------------------ GEMM + bias
// C[z] = X[z] @ Wsum[z] + bias[z],  X0=atoms, X1=amino
// grid: (DIM/BN, M_ROWS/BM, 2), block: 256 (16x16), each thread: 8x8 tile
__global__ __launch_bounds__(256, 2)
void gemm_bias_kernel(const float* __restrict__ atoms,
                      const float* __restrict__ amino,
                      const float* __restrict__ bcc,
                      const float* __restrict__ bcp,
                      float* __restrict__ out) {
    const int z = blockIdx.z;
    const float* __restrict__ X    = (z == 0) ? atoms : amino;
    const float* __restrict__ W    = g_Wsum[z];
    const float* __restrict__ bias = (z == 0) ? bcc : bcp;
    float* __restrict__ C = out + (size_t)z * (size_t)M_ROWS * DIM;

    __shared__ float As[BK][BM + 4];   // transposed A tile, padded (bank spread)
    __shared__ float Bs[BK][BN];

    const int tid  = threadIdx.x;
    const int tx   = tid & 15;         // 0..15  (N direction)
    const int ty   = tid >> 4;         // 0..15  (M direction)
    const int row0 = blockIdx.y * BM;
    const int col0 = blockIdx.x * BN;

    unsigned long long acc[TM][TN / 2];
#pragma unroll
    for (int i = 0; i < TM; i++)
#pragma unroll
        for (int j = 0; j < TN / 2; j++) acc[i][j] = 0ull;   // (0.0f, 0.0f)

    for (int kt = 0; kt < DIM; kt += BK) {
        // ---- stage A tile [BM x BK], stored transposed As[k][m]
#pragma unroll
        for (int l = 0; l < 2; l++) {
            int fidx = tid + l * 256;          // 0..511 float4 slots
            int ar   = fidx >> 2;              // row within tile 0..127
            int ak   = (fidx & 3) * 4;         // k offset 0,4,8,12
            float4 v = *reinterpret_cast<const float4*>(
                &X[(size_t)(row0 + ar) * DIM + kt + ak]);
            As[ak + 0][ar] = v.x;
            As[ak + 1][ar] = v.y;
            As[ak + 2][ar] = v.z;
            As[ak + 3][ar] = v.w;
        }
        // ---- stage B tile [BK x BN]
#pragma unroll
        for (int l = 0; l < 2; l++) {
            int fidx = tid + l * 256;
            int br   = fidx >> 5;              // 0..15
            int bc   = (fidx & 31) * 4;        // 0..124
            *reinterpret_cast<float4*>(&Bs[br][bc]) =
                *reinterpret_cast<const float4*>(
                    &W[(size_t)(kt + br) * DIM + col0 + bc]);
        }
        __syncthreads();

#pragma unroll
        for (int kk = 0; kk < BK; kk++) {
            float4 a0 = *reinterpret_cast<const float4*>(&As[kk][ty * TM]);
            float4 a1 = *reinterpret_cast<const float4*>(&As[kk][ty * TM + 4]);
            const unsigned long long* bp =
                reinterpret_cast<const unsigned long long*>(&Bs[kk][tx * TN]);
            unsigned long long b0 = bp[0], b1 = bp[1], b2 = bp[2], b3 = bp[3];
            float a[TM] = {a0.x, a0.y, a0.z, a0.w, a1.x, a1.y, a1.z, a1.w};
#pragma unroll
            for (int i = 0; i < TM; i++) {
                unsigned long long av = pack2(a[i], a[i]);
                ffma2(acc[i][0], av, b0);
                ffma2(acc[i][1], av, b1);
                ffma2(acc[i][2], av, b2);
                ffma2(acc[i][3], av, b3);
            }
        }
        __syncthreads();
    }

    // ---- epilogue: +bias, packed stores (pair layout == consecutive floats)
    const unsigned long long* bb =
        reinterpret_cast<const unsigned long long*>(&bias[col0 + tx * TN]);
    unsigned long long bias2[4] = {bb[0], bb[1], bb[2], bb[3]};
#pragma unroll
    for (int i = 0; i < TM; i++) {
        const int row = row0 + ty * TM + i;
        unsigned long long r0 = add2(acc[i][0], bias2[0]);
        unsigned long long r1 = add2(acc[i][1], bias2[1]);
        unsigned long long r2 = add2(acc[i][2], bias2[2]);
        unsigned long long r3 = add2(acc[i][3], bias2[3]);
        ulonglong2 s0; s0.x = r0; s0.y = r1;
        ulonglong2 s1; s1.x = r2; s1.y = r3;
        float* cp = &C[(size_t)row * DIM + col0 + tx * TN];
        *reinterpret_cast<ulonglong2*>(cp)     = s0;
        *reinterpret_cast<ulonglong2*>(cp + 4) = s1;
    }
}

// ------------------------------------------------------------------ launch
extern "C" void kernel_launch(void* const* d_in, const int* in_sizes, int n_in,
                              void* d_out, int out_size) {
    // metadata order:
    // 0 atoms_vector, 1 amino_vector, 2 U, 3 Wp2c, 4 bp2c, 5 Wc2p, 6 bc2p,
    // 7 Whc, 8 bhc, 9 Whp, 10 bhp, 11 Wac, 12 bac, 13 Wap, 14 bap,
    // 15 Wcc, 16 bcc, 17 Wcp, 18 bcp
    const float* atoms = (const float*)d_in[0];
    const float* amino = (const float*)d_in[1];
    const float* Wcc   = (const float*)d_in[15];
    const float* bcc   = (const float*)d_in[16];
    const float* Wcp   = (const float*)d_in[17];
    const float* bcp   = (const float*)d_in[18];
    float* out = (float*)d_out;

    fold_weights_kernel<<<(DIM * DIM + 255) / 256, 256>>>(Wcc, Wcp);

    dim3 grid(DIM / BN, M_ROWS / BM, 2);   // 4 x 48 x 2 = 384 CTAs
    gemm_bias_kernel<<<grid, 256>>>(atoms, amino, bcc, bcp, out);
}

// round 4
// speedup vs baseline: 2.1620x; 2.1620x over previous
#include <cuda_runtime.h>
#include <cuda_bf16.h>
#include <cstdint>

// BiATT algebraic collapse: softmax over axis=1 of a [N,1] tensor == 1.0, so
// all four bi-attention branches are identity. cf = atoms @ (sum Wcc blocks) + bcc,
// pf = amino @ (sum Wcp blocks) + bcp  =>  two [6144x512]@[512x512] fp32 GEMMs.
// Tensor path: 3-way bf16 split  A@W ~= Ah@Wh + Al@Wh + Ah@Wl, fp32 accum,
// via mma.sync.m16n8k16 (baseline PTX — tcgen05 is rejected by this harness's
// .target sm_103 ptxas pass).
// B is [N][K] row-major == col-major KxN => NON-trans ldmatrix (R3 bug: .trans).

#define DIM     512
#define M_ROWS  6144
#define BM      128
#define BN      128
#define BK      32
#define NCHUNK  (DIM / BK)     // 16

// folded + transposed [N x K] K-major bf16 weight splits
__device__ __nv_bfloat16 g_Wh[2][DIM * DIM];
__device__ __nv_bfloat16 g_Wl[2][DIM * DIM];

// ---- smem layout: rows of 32 bf16 padded to 80 B (conflict-free ldmatrix)
#define PITCH   80
#define SM_AH   0
#define SM_AL   (SM_AH + BM * PITCH)     // 10240
#define SM_BH   (SM_AL + BM * PITCH)     // 20480
#define SM_BL   (SM_BH + BN * PITCH)     // 30720
#define SM_BIAS (SM_BL + BN * PITCH)     // 40960
#define SM_TOT  (SM_BIAS + 512)          // 41472 (< 48KB static)

// ---------------------------------------------------------------- helpers
__device__ __forceinline__ uint32_t smem_u32(const void* p) {
    return (uint32_t)__cvta_generic_to_shared(p);
}
__device__ __forceinline__ uint32_t pack_bf2(__nv_bfloat16 a, __nv_bfloat16 b) {
    __nv_bfloat162 t(a, b);
    return *reinterpret_cast<uint32_t*>(&t);
}
__device__ __forceinline__ void ldsm_x4(uint32_t* r, uint32_t addr) {
    asm volatile("ldmatrix.sync.aligned.m8n8.x4.shared.b16 {%0,%1,%2,%3}, [%4];"
                 : "=r"(r[0]), "=r"(r[1]), "=r"(r[2]), "=r"(r[3]) : "r"(addr));
}
__device__ __forceinline__ void mma_bf16(float* d, const uint32_t* a,
                                         uint32_t b0, uint32_t b1) {
    asm volatile(
        "mma.sync.aligned.m16n8k16.row.col.f32.bf16.bf16.f32 "
        "{%0,%1,%2,%3}, {%4,%5,%6,%7}, {%8,%9}, {%0,%1,%2,%3};"
        : "+f"(d[0]), "+f"(d[1]), "+f"(d[2]), "+f"(d[3])
        : "r"(a[0]), "r"(a[1]), "r"(a[2]), "r"(a[3]), "r"(b0), "r"(b1));
}

// ----------------------------------------------- prologue: fold + T + split
// g_Wh/g_Wl[z][n*512+k] = bf16 hi/lo of sum_b Wsrc[(b*512+k)*512+n]
__global__ void fold_split_kernel(const float* __restrict__ Wcc,
                                  const float* __restrict__ Wcp) {
    __shared__ float s[32][33];
    const int z = blockIdx.z;
    const float* __restrict__ W = z ? Wcp : Wcc;
    const int k = blockIdx.y * 32 + threadIdx.y;
    const int n = blockIdx.x * 32 + threadIdx.x;
    float v = 0.f;
#pragma unroll
    for (int b = 0; b < 4; b++) v += W[(size_t)(b * DIM + k) * DIM + n];
    s[threadIdx.y][threadIdx.x] = v;
    __syncthreads();
    const int n2 = blockIdx.x * 32 + threadIdx.y;
    const int k2 = blockIdx.y * 32 + threadIdx.x;
    const float val = s[threadIdx.x][threadIdx.y];
    __nv_bfloat16 h = __float2bfloat16(val);
    __nv_bfloat16 l = __float2bfloat16(val - __bfloat162float(h));
    g_Wh[z][(size_t)n2 * DIM + k2] = h;
    g_Wl[z][(size_t)n2 * DIM + k2] = l;
}

// --------------------------------------------------- HMMA GEMM + bias
// grid (4, 48, 2), 256 threads; warp tile 64x32 (2x4 warp grid)
__global__ void __launch_bounds__(256, 2)
biatt_gemm_kernel(const float* __restrict__ atoms,
                  const float* __restrict__ amino,
                  const float* __restrict__ bcc,
                  const float* __restrict__ bcp,
                  float* __restrict__ out) {
    __shared__ __align__(16) char sm[SM_TOT];
    const uint32_t sbase = smem_u32(sm);

    const int tid  = threadIdx.x;
    const int wid  = tid >> 5;
    const int lane = tid & 31;
    const int z    = blockIdx.z;
    const int n0   = blockIdx.x * BN;
    const int m0   = blockIdx.y * BM;
    const int mw   = (wid >> 2) * 64;       // warp m offset
    const int nw   = (wid & 3) * 32;        // warp n offset

    const float* __restrict__ X    = z ? amino : atoms;
    const float* __restrict__ bias = z ? bcp : bcc;
    const __nv_bfloat16* __restrict__ Wh = g_Wh[z];
    const __nv_bfloat16* __restrict__ Wl = g_Wl[z];

    if (tid < 32) {   // stage bias slice [n0, n0+128)
        float4 bv = *reinterpret_cast<const float4*>(&bias[n0 + tid * 4]);
        *reinterpret_cast<float4*>(sm + SM_BIAS + tid * 16) = bv;
    }

    // ldmatrix lane address offsets
    // A tile (16 rows x 32B): lanes 0-15 -> rows, col 0; lanes 16-31 -> col 16B
    const uint32_t aRowOff =
        (uint32_t)((mw + (lane & 15)) * PITCH + ((lane >> 4) << 4));
    // B tile (16 n-rows x 32B): lanes 0-7 n0-7/k0-7, 8-15 n0-7/k8-15,
    //                           16-23 n8-15/k0-7, 24-31 n8-15/k8-15
    const uint32_t bRowOff =
        (uint32_t)((nw + ((lane >> 4) << 3) + (lane & 7)) * PITCH +
                   (((lane >> 3) & 1) << 4));
    const uint32_t aH = sbase + SM_AH + aRowOff;
    const uint32_t aL = sbase + SM_AL + aRowOff;
    const uint32_t bH = sbase + SM_BH + bRowOff;
    const uint32_t bL = sbase + SM_BL + bRowOff;

    float acc[4][4][4];
#pragma unroll
    for (int i = 0; i < 4; i++)
#pragma unroll
        for (int j = 0; j < 4; j++)
#pragma unroll
            for (int e = 0; e < 4; e++) acc[i][j][e] = 0.f;

    for (int c = 0; c < NCHUNK; ++c) {
        const int kc = c * BK;
        // ---- A: LDG fp32, split bf16 hi/lo, STS (8 floats / slot)
#pragma unroll
        for (int l = 0; l < 2; ++l) {
            const int fidx = tid + l * 256;       // 512 slots
            const int row  = fidx >> 2;
            const int seg  = fidx & 3;            // 8 floats each
            const float* src = &X[(size_t)(m0 + row) * DIM + kc + seg * 8];
            float4 v0 = *reinterpret_cast<const float4*>(src);
            float4 v1 = *reinterpret_cast<const float4*>(src + 4);
            float f[8] = {v0.x, v0.y, v0.z, v0.w, v1.x, v1.y, v1.z, v1.w};
            uint32_t hi[4], lo[4];
#pragma unroll
            for (int p = 0; p < 4; ++p) {
                __nv_bfloat16 h0 = __float2bfloat16(f[2 * p]);
                __nv_bfloat16 h1 = __float2bfloat16(f[2 * p + 1]);
                __nv_bfloat16 l0 = __float2bfloat16(f[2 * p] - __bfloat162float(h0));
                __nv_bfloat16 l1 = __float2bfloat16(f[2 * p + 1] - __bfloat162float(h1));
                hi[p] = pack_bf2(h0, h1);
                lo[p] = pack_bf2(l0, l1);
            }
            const int off = row * PITCH + seg * 16;
            *reinterpret_cast<uint4*>(sm + SM_AH + off) =
                make_uint4(hi[0], hi[1], hi[2], hi[3]);
            *reinterpret_cast<uint4*>(sm + SM_AL + off) =
                make_uint4(lo[0], lo[1], lo[2], lo[3]);
        }
        // ---- B: bf16 copy (both splits)
#pragma unroll
        for (int l = 0; l < 2; ++l) {
            const int fidx = tid + l * 256;       // 512 slots
            const int row  = fidx >> 2;
            const int seg  = fidx & 3;            // 8 bf16 each
            const size_t src = (size_t)(n0 + row) * DIM + kc + seg * 8;
            const int off = row * PITCH + seg * 16;
            *reinterpret_cast<uint4*>(sm + SM_BH + off) =
                *reinterpret_cast<const uint4*>(&Wh[src]);
            *reinterpret_cast<uint4*>(sm + SM_BL + off) =
                *reinterpret_cast<const uint4*>(&Wl[src]);
        }
        __syncthreads();

#pragma unroll
        for (int ks = 0; ks < 2; ++ks) {
            const uint32_t ko = ks * 32;          // 16 bf16 = 32 B
            uint32_t ah[4][4], al4[4][4];
#pragma unroll
            for (int mt = 0; mt < 4; ++mt) ldsm_x4(ah[mt],  aH + mt * (16 * PITCH) + ko);
#pragma unroll
            for (int mt = 0; mt < 4; ++mt) ldsm_x4(al4[mt], aL + mt * (16 * PITCH) + ko);
#pragma unroll
            for (int j2 = 0; j2 < 2; ++j2) {
                uint32_t bh4[4], bl4[4];
                ldsm_x4(bh4, bH + j2 * (16 * PITCH) + ko);   // non-trans: [N][K] == col-major KxN
                ldsm_x4(bl4, bL + j2 * (16 * PITCH) + ko);
#pragma unroll
                for (int mt = 0; mt < 4; ++mt) {
                    float* d0 = acc[mt][j2 * 2];
                    float* d1 = acc[mt][j2 * 2 + 1];
                    mma_bf16(d0, ah[mt],  bh4[0], bh4[1]);
                    mma_bf16(d1, ah[mt],  bh4[2], bh4[3]);
                    mma_bf16(d0, al4[mt], bh4[0], bh4[1]);
                    mma_bf16(d1, al4[mt], bh4[2], bh4[3]);
                    mma_bf16(d0, ah[mt],  bl4[0], bl4[1]);
                    mma_bf16(d1, ah[mt],  bl4[2], bl4[3]);
                }
            }
        }
        __syncthreads();
    }

    // ---- epilogue: +bias, float2 stores
    float* C = out + (size_t)z * M_ROWS * DIM;
    const float* sb = reinterpret_cast<const float*>(sm + SM_BIAS);
#pragma unroll
    for (int mt = 0; mt < 4; ++mt) {
        const int r0 = m0 + mw + mt * 16 + (lane >> 2);
#pragma unroll
        for (int nt = 0; nt < 4; ++nt) {
            const int cl = nw + nt * 8 + (lane & 3) * 2;   // within [0,128)
            const float b0 = sb[cl], b1 = sb[cl + 1];
            float2 v0 = make_float2(acc[mt][nt][0] + b0, acc[mt][nt][1] + b1);
            float2 v1 = make_float2(acc[mt][nt][2] + b0, acc[mt][nt][3] + b1);
            *reinterpret_cast<float2*>(&C[(size_t)r0 * DIM + n0 + cl]) = v0;
            *reinterpret_cast<float2*>(&C[(size_t)(r0 + 8) * DIM + n0 + cl]) = v1;
        }
    }
}

// ------------------------------------------------------------------ launch
extern "C" void kernel_launch(void* const* d_in, const int* in_sizes, int n_in,
                              void* d_out, int out_size) {
    const float* atoms = (const float*)d_in[0];
    const float* amino = (const float*)d_in[1];
    const float* Wcc   = (const float*)d_in[15];
    const float* bcc   = (const float*)d_in[16];
    const float* Wcp   = (const float*)d_in[17];
    const float* bcp   = (const float*)d_in[18];
    float* out = (float*)d_out;

    fold_split_kernel<<<dim3(16, 16, 2), dim3(32, 32)>>>(Wcc, Wcp);

    dim3 grid(DIM / BN, M_ROWS / BM, 2);   // 4 x 48 x 2 = 384 CTAs
    biatt_gemm_kernel<<<grid, 256>>>(atoms, amino, bcc, bcp, out);
}